// round 4
// baseline (speedup 1.0000x reference)
#include <cuda_runtime.h>
#include <cstdint>

// ---------------------------------------------------------------------------
// GAT collapses (uniform per-item node features; per-dst softmax weights sum
// to 1 via self-loops) => whole model = 7-layer MLP on 64 batch rows.
// 16 independent clusters (8 CTAs x 256 thr), one per 4 batch rows.
// Layers exchanged via DSMEM replicated stores + barrier.cluster (no global
// barriers, no device globals). f32x2 FFMA2 dot products.
// ---------------------------------------------------------------------------

typedef unsigned long long ULL;
typedef unsigned int U32;

#define RS 324   // act row stride in floats (81 quads -> rows hit distinct banks)

__device__ __forceinline__ void ffma2(ULL& d, ULL a, ULL b) {
    asm("fma.rn.f32x2 %0, %1, %2, %0;" : "+l"(d) : "l"(a), "l"(b));
}
__device__ __forceinline__ float2 unpack2f(ULL v) {
    float2 f; asm("mov.b64 {%0, %1}, %2;" : "=f"(f.x), "=f"(f.y) : "l"(v)); return f;
}

#define CLUSTER_SYNC() do { \
    asm volatile("barrier.cluster.arrive.aligned;" ::: "memory"); \
    asm volatile("barrier.cluster.wait.aligned;"   ::: "memory"); \
} while (0)

__device__ __forceinline__ U32 smem_u32(const void* p) {
    U32 a;
    asm("{ .reg .u64 t64; cvta.to.shared.u64 t64, %1; cvt.u32.u64 %0, t64; }"
        : "=r"(a) : "l"(p));
    return a;
}

// Q quads of dual-lane FFMA2 dot; W from gmem (warp-broadcast), A from smem.
template<int Q>
__device__ __forceinline__ float dotQ(const float* __restrict__ Wp,
                                      const float* __restrict__ Ap) {
    const longlong2* w = (const longlong2*)Wp;
    const longlong2* a = (const longlong2*)Ap;
    ULL s0 = 0ull, s1 = 0ull;
    #pragma unroll
    for (int i = 0; i < Q; i++) {
        longlong2 wv = w[i];
        longlong2 av = a[i];
        ffma2(s0, (ULL)wv.x, (ULL)av.x);
        ffma2(s1, (ULL)wv.y, (ULL)av.y);
    }
    float2 f0 = unpack2f(s0), f1 = unpack2f(s1);
    return (f0.x + f0.y) + (f1.x + f1.y);
}

// One layer: thread covers K/2 of the dot for (out_f, row r); kh==0 lane
// combines via shfl and broadcast-stores relu(result+bias) into all 8 CTAs.
template<int K>
__device__ __forceinline__ void layerT(const float* __restrict__ Wrow, float bias,
                                       const float* __restrict__ Sin,
                                       const U32* __restrict__ rdst,
                                       int r, int kh, U32 off_res) {
    float s = dotQ<K / 8>(Wrow + kh * (K / 2), Sin + r * RS + kh * (K / 2));
    s += __shfl_xor_sync(0xffffffffu, s, 4);
    if (kh == 0) {
        float v = fmaxf(s + bias, 0.f);
        #pragma unroll
        for (int k = 0; k < 8; k++)
            asm volatile("st.shared::cluster.f32 [%0], %1;"
                         :: "r"(rdst[k] + off_res), "f"(v) : "memory");
    }
}

__global__ __launch_bounds__(256, 1) __cluster_dims__(8, 1, 1)
void net_kernel(
    const float* __restrict__ x, const int* __restrict__ cidx,
    const float* __restrict__ W_in, const float* __restrict__ b_in,
    const float* __restrict__ gat_W, const float* __restrict__ gat_b,
    const float* __restrict__ emb,
    const float* __restrict__ W_fuse, const float* __restrict__ b_fuse,
    const float* __restrict__ W_p1, const float* __restrict__ b_p1,
    const float* __restrict__ W_p2, const float* __restrict__ b_p2,
    const float* __restrict__ W_p3, const float* __restrict__ b_p3,
    const float* __restrict__ W_d1, const float* __restrict__ b_d1,
    const float* __restrict__ W_d2, const float* __restrict__ b_d2,
    const float* __restrict__ W_d3, const float* __restrict__ b_d3,
    float* __restrict__ out) {

    __shared__ __align__(16) float Sa[4 * RS];
    __shared__ __align__(16) float Sb[4 * RS];
    __shared__ float s2[64];

    const int t    = threadIdx.x;
    const int lane = t & 31;
    const int w    = t >> 5;
    U32 rank; asm("mov.u32 %0, %%cluster_ctarank;" : "=r"(rank));
    const int c     = blockIdx.x >> 3;       // cluster id = 4-row group
    const int r     = lane & 3;              // local batch row 0..3
    const int kh    = (lane >> 2) & 1;       // K half
    const int oo    = lane >> 3;             // out-within-warp 0..3
    const int out_f = (int)rank * 32 + w * 4 + oo;  // output feature 0..255
    const U32 off_res = (U32)(r * RS + out_f) * 4u;

    // Precompute DSMEM base addresses of Sa/Sb in all 8 cluster CTAs.
    U32 ua = smem_u32(Sa), ub = smem_u32(Sb);
    U32 ra[8], rb[8];
    #pragma unroll
    for (int k = 0; k < 8; k++) {
        asm("mapa.shared::cluster.u32 %0, %1, %2;" : "=r"(ra[k]) : "r"(ua), "r"(k));
        asm("mapa.shared::cluster.u32 %0, %1, %2;" : "=r"(rb[k]) : "r"(ub), "r"(k));
    }

    // ---- stage x (k 0..63) and emb[cidx] (k 256..319) into local Sa ----
    if (t < 64) {
        int rr = t >> 4, q = t & 15;
        ((float4*)(Sa + rr * RS))[q] = ((const float4*)x)[(c * 4 + rr) * 16 + q];
    } else if (t < 128) {
        int i = t - 64, rr = i >> 4, q = i & 15;
        int ci = cidx[c * 4 + rr];
        ((float4*)(Sa + rr * RS + 256))[q] = ((const float4*)emb)[ci * 16 + q];
    }
    __syncthreads();

    // ---- L0: relu(W_in x + b), K=64 : Sa -> Sb ----
    layerT<64>(W_in + out_f * 64, b_in[out_f], Sa, rb, r, kh, off_res);
    CLUSTER_SYNC();
    // ---- L1..L3: collapsed GAT [256x256] ----
    layerT<256>(gat_W + out_f * 256, gat_b[out_f], Sb, ra, r, kh, off_res);
    CLUSTER_SYNC();
    layerT<256>(gat_W + 65536 + out_f * 256, gat_b[256 + out_f], Sa, rb, r, kh, off_res);
    CLUSTER_SYNC();
    layerT<256>(gat_W + 131072 + out_f * 256, gat_b[512 + out_f], Sb, ra, r, kh, off_res);
    CLUSTER_SYNC();
    // ---- L4: fuse [256x320] over [g3 ; emb] (emb pre-staged in Sa 256..319) ----
    layerT<320>(W_fuse + out_f * 320, b_fuse[out_f], Sa, rb, r, kh, off_res);
    CLUSTER_SYNC();
    // ---- L5: heads stage1 [p1 ; d1] = [256x256] : Sb -> Sa ----
    {
        const float* W5 = (out_f < 128) ? (W_p1 + out_f * 256)
                                        : (W_d1 + (out_f - 128) * 256);
        float b5 = (out_f < 128) ? b_p1[out_f] : b_d1[out_f - 128];
        layerT<256>(W5, b5, Sb, ra, r, kh, off_res);
    }
    CLUSTER_SYNC();

    // ---- Tail (local only): rank -> (head, row); p2/d2 K=128, then 64-dot ----
    {
        const int head = (int)rank >> 2;      // 0 = price, 1 = direction
        const int row  = (int)rank & 3;
        const int o2   = t >> 2;              // 0..63
        const int ks   = t & 3;               // K quarter
        const float* W2 = head ? W_d2 : W_p2;
        const float* b2 = head ? b_d2 : b_p2;
        float s = dotQ<8>(W2 + o2 * 128 + ks * 32,
                          Sa + row * RS + head * 128 + ks * 32);
        s += __shfl_xor_sync(0xffffffffu, s, 1);
        s += __shfl_xor_sync(0xffffffffu, s, 2);
        if (ks == 0) s2[o2] = fmaxf(s + b2[o2], 0.f);
        __syncthreads();

        if (w == 0) {
            const float* W3 = head ? W_d3 : W_p3;
            float s3 = W3[lane] * s2[lane] + W3[lane + 32] * s2[lane + 32];
            #pragma unroll
            for (int m = 16; m; m >>= 1)
                s3 += __shfl_xor_sync(0xffffffffu, s3, m);
            if (lane == 0) {
                int rg = c * 4 + row;
                if (head == 0) out[rg] = s3 + b_p3[0];
                else out[64 + rg] = 1.f / (1.f + __expf(-(s3 + b_d3[0])));
            }
        }
    }
}

extern "C" void kernel_launch(void* const* d_in, const int* in_sizes, int n_in,
                              void* d_out, int out_size) {
    const float* x      = (const float*)d_in[0];
    const int*   cidx   = (const int*)  d_in[1];
    // d_in[2] edge_index, d_in[3] edge_attr: unused (softmax collapse)
    const float* W_in   = (const float*)d_in[4];
    const float* b_in   = (const float*)d_in[5];
    const float* gat_W  = (const float*)d_in[6];
    // d_in[7..10]: attention params — unused (collapse)
    const float* gat_b  = (const float*)d_in[11];
    const float* emb    = (const float*)d_in[12];
    const float* W_fuse = (const float*)d_in[13];
    const float* b_fuse = (const float*)d_in[14];
    const float* W_p1   = (const float*)d_in[15];
    const float* b_p1   = (const float*)d_in[16];
    const float* W_p2   = (const float*)d_in[17];
    const float* b_p2   = (const float*)d_in[18];
    const float* W_p3   = (const float*)d_in[19];
    const float* b_p3   = (const float*)d_in[20];
    const float* W_d1   = (const float*)d_in[21];
    const float* b_d1   = (const float*)d_in[22];
    const float* W_d2   = (const float*)d_in[23];
    const float* b_d2   = (const float*)d_in[24];
    const float* W_d3   = (const float*)d_in[25];
    const float* b_d3   = (const float*)d_in[26];

    net_kernel<<<128, 256>>>(x, cidx, W_in, b_in, gat_W, gat_b, emb,
                             W_fuse, b_fuse, W_p1, b_p1, W_p2, b_p2,
                             W_p3, b_p3, W_d1, b_d1, W_d2, b_d2,
                             W_d3, b_d3, (float*)d_out);
}

// round 5
// speedup vs baseline: 2.1605x; 2.1605x over previous
#include <cuda_runtime.h>

// ---------------------------------------------------------------------------
// GAT collapses (uniform per-item node features; per-dst softmax weights sum
// to 1 via self-loops) => whole model = 7-layer MLP on 64 batch rows.
// Fully block-local: 32 blocks x 512 threads, block bx owns batch rows
// {2bx, 2bx+1}; only __syncthreads() between layers. Warp = 4 outputs x
// 8-lane K-split, coalesced LDG.128 weights, acts reg-cached, FFMA2 math.
// ---------------------------------------------------------------------------

typedef unsigned long long ULL;

__device__ __forceinline__ void ffma2(ULL& d, ULL a, ULL b) {
    asm("fma.rn.f32x2 %0, %1, %2, %0;" : "+l"(d) : "l"(a), "l"(b));
}
__device__ __forceinline__ void fadd2(ULL& d, ULL a) {
    asm("add.rn.f32x2 %0, %1, %0;" : "+l"(d) : "l"(a));
}
__device__ __forceinline__ float2 unpack2f(ULL v) {
    float2 f; asm("mov.b64 {%0, %1}, %2;" : "=f"(f.x), "=f"(f.y) : "l"(v)); return f;
}

// Load NQ quads per row (lane covers quads s+8i) from smem into ULL pairs.
template<int NQ>
__device__ __forceinline__ void load_acts(const float* __restrict__ S0,
                                          const float* __restrict__ S1,
                                          int s, ULL* a0, ULL* a1) {
    #pragma unroll
    for (int i = 0; i < NQ; i++) {
        longlong2 v0 = ((const longlong2*)S0)[s + 8 * i];
        longlong2 v1 = ((const longlong2*)S1)[s + 8 * i];
        a0[2 * i] = (ULL)v0.x; a0[2 * i + 1] = (ULL)v0.y;
        a1[2 * i] = (ULL)v1.x; a1[2 * i + 1] = (ULL)v1.y;
    }
}

// Partial dual-row dot over this lane's NQ quads of weight row Wrow.
template<int NQ>
__device__ __forceinline__ float2 dotw(const float* __restrict__ Wrow, int s,
                                       const ULL* a0, const ULL* a1) {
    const longlong2* wq = (const longlong2*)Wrow;
    ULL p0 = 0ull, q0 = 0ull, p1 = 0ull, q1 = 0ull;
    #pragma unroll
    for (int i = 0; i < NQ; i++) {
        longlong2 wv = wq[s + 8 * i];
        ffma2(p0, (ULL)wv.x, a0[2 * i]);
        ffma2(q0, (ULL)wv.y, a0[2 * i + 1]);
        ffma2(p1, (ULL)wv.x, a1[2 * i]);
        ffma2(q1, (ULL)wv.y, a1[2 * i + 1]);
    }
    fadd2(p0, q0); fadd2(p1, q1);
    float2 f0 = unpack2f(p0), f1 = unpack2f(p1);
    return make_float2(f0.x + f0.y, f1.x + f1.y);
}

// 8-lane tree-reduce both rows; lane s==0 writes relu(v+bias).
__device__ __forceinline__ void redstore(float2 v, float bias, int s,
                                         float* __restrict__ O0,
                                         float* __restrict__ O1, int o) {
    #pragma unroll
    for (int m = 1; m <= 4; m <<= 1) {
        v.x += __shfl_xor_sync(0xffffffffu, v.x, m);
        v.y += __shfl_xor_sync(0xffffffffu, v.y, m);
    }
    if (s == 0) {
        O0[o] = fmaxf(v.x + bias, 0.f);
        O1[o] = fmaxf(v.y + bias, 0.f);
    }
}

// Standard 256-output layer, K = NQ*32 (acts fully reg-cached).
template<int NQ>
__device__ __forceinline__ void layer256(const float* __restrict__ W, int K,
                                         const float* __restrict__ bias,
                                         const float* __restrict__ S0,
                                         const float* __restrict__ S1,
                                         float* __restrict__ O0,
                                         float* __restrict__ O1,
                                         int w, int s, int grp) {
    ULL a0[2 * NQ], a1[2 * NQ];
    load_acts<NQ>(S0, S1, s, a0, a1);
    #pragma unroll
    for (int j = 0; j < 4; j++) {
        int o = w * 16 + j * 4 + grp;
        float2 v = dotw<NQ>(W + o * K, s, a0, a1);
        redstore(v, bias[o], s, O0, O1, o);
    }
}

__global__ __launch_bounds__(512, 1) void net_kernel(
    const float* __restrict__ x, const int* __restrict__ cidx,
    const float* __restrict__ W_in, const float* __restrict__ b_in,
    const float* __restrict__ gat_W, const float* __restrict__ gat_b,
    const float* __restrict__ emb,
    const float* __restrict__ W_fuse, const float* __restrict__ b_fuse,
    const float* __restrict__ W_p1, const float* __restrict__ b_p1,
    const float* __restrict__ W_p2, const float* __restrict__ b_p2,
    const float* __restrict__ W_p3, const float* __restrict__ b_p3,
    const float* __restrict__ W_d1, const float* __restrict__ b_d1,
    const float* __restrict__ W_d2, const float* __restrict__ b_d2,
    const float* __restrict__ W_d3, const float* __restrict__ b_d3,
    float* __restrict__ out) {

    __shared__ __align__(16) float X[2][64];
    __shared__ __align__(16) float A[2][336];
    __shared__ __align__(16) float B[2][336];
    __shared__ __align__(16) float C[2][128];

    const int t    = threadIdx.x;
    const int bx   = blockIdx.x;
    const int lane = t & 31;
    const int w    = t >> 5;       // warp 0..15
    const int s    = lane & 7;     // K-slice within 8-lane group
    const int grp  = lane >> 3;    // output-within-iter 0..3

    // ---- stage inputs: x rows -> X; emb[cidx] -> B[r][256..319] ----
    if (t < 32) {
        int r = t >> 4, q = t & 15;
        ((float4*)X[r])[q] = ((const float4*)x)[(2 * bx + r) * 16 + q];
    } else if (t < 64) {
        int i = t - 32, r = i >> 4, q = i & 15;
        int ci = cidx[2 * bx + r];
        ((float4*)(B[r] + 256))[q] = ((const float4*)emb)[ci * 16 + q];
    }
    __syncthreads();

    // L0: [256 x 64]  X -> A
    layer256<2>(W_in, 64, b_in, X[0], X[1], A[0], A[1], w, s, grp);
    __syncthreads();
    // L1-L3: collapsed GAT [256 x 256]
    layer256<8>(gat_W,          256, gat_b,       A[0], A[1], B[0], B[1], w, s, grp);
    __syncthreads();
    layer256<8>(gat_W +  65536, 256, gat_b + 256, B[0], B[1], A[0], A[1], w, s, grp);
    __syncthreads();
    layer256<8>(gat_W + 131072, 256, gat_b + 512, A[0], A[1], B[0], B[1], w, s, grp);
    __syncthreads();

    // L4: fuse [256 x 320] over [g3 ; emb]  B -> A   (chunked: 256 + 64)
    {
        ULL a0[16], a1[16], e0[4], e1[4];
        load_acts<8>(B[0], B[1], s, a0, a1);
        load_acts<2>(B[0] + 256, B[1] + 256, s, e0, e1);
        #pragma unroll
        for (int j = 0; j < 4; j++) {
            int o = w * 16 + j * 4 + grp;
            float2 v  = dotw<8>(W_fuse + o * 320,       s, a0, a1);
            float2 v2 = dotw<2>(W_fuse + o * 320 + 256, s, e0, e1);
            v.x += v2.x; v.y += v2.y;
            redstore(v, b_fuse[o], s, A[0], A[1], o);
        }
    }
    __syncthreads();

    // L5: heads stage1 [p1 ; d1] = [256 x 256]  A -> B
    {
        ULL a0[16], a1[16];
        load_acts<8>(A[0], A[1], s, a0, a1);
        #pragma unroll
        for (int j = 0; j < 4; j++) {
            int o = w * 16 + j * 4 + grp;
            const float* W5 = (o < 128) ? (W_p1 + o * 256) : (W_d1 + (o - 128) * 256);
            float b5        = (o < 128) ? b_p1[o] : b_d1[o - 128];
            float2 v = dotw<8>(W5, s, a0, a1);
            redstore(v, b5, s, B[0], B[1], o);
        }
    }
    __syncthreads();

    // L6: p2 (warps 0-7) / d2 (warps 8-15), each [64 x 128]  B -> C
    {
        const bool is_d = (w >= 8);
        const int hb = is_d ? 128 : 0;
        const float* W2 = is_d ? W_d2 : W_p2;
        const float* b2 = is_d ? b_d2 : b_p2;
        ULL a0[8], a1[8];
        load_acts<4>(B[0] + hb, B[1] + hb, s, a0, a1);
        #pragma unroll
        for (int j = 0; j < 2; j++) {
            int o  = w * 8 + j * 4 + grp;          // 0..127 (C index)
            int ol = o - (is_d ? 64 : 0);          // local 0..63
            float2 v = dotw<4>(W2 + ol * 128, s, a0, a1);
            redstore(v, b2[ol], s, C[0], C[1], o);
        }
    }
    __syncthreads();

    // L7: final 64-dots; warps 0-3 = {row0 price, row0 dir, row1 price, row1 dir}
    if (w < 4) {
        const int r = w >> 1, is_d = w & 1;
        const float* W3 = is_d ? W_d3 : W_p3;
        const float* Cv = C[r] + is_d * 64;
        float v = W3[lane] * Cv[lane] + W3[lane + 32] * Cv[lane + 32];
        #pragma unroll
        for (int m = 16; m; m >>= 1)
            v += __shfl_xor_sync(0xffffffffu, v, m);
        if (lane == 0) {
            int rg = 2 * bx + r;
            if (!is_d) out[rg] = v + b_p3[0];
            else       out[64 + rg] = 1.f / (1.f + __expf(-(v + b_d3[0])));
        }
    }
}

extern "C" void kernel_launch(void* const* d_in, const int* in_sizes, int n_in,
                              void* d_out, int out_size) {
    const float* x      = (const float*)d_in[0];
    const int*   cidx   = (const int*)  d_in[1];
    // d_in[2] edge_index, d_in[3] edge_attr: unused (softmax collapse)
    const float* W_in   = (const float*)d_in[4];
    const float* b_in   = (const float*)d_in[5];
    const float* gat_W  = (const float*)d_in[6];
    // d_in[7..10]: attention params — unused (collapse)
    const float* gat_b  = (const float*)d_in[11];
    const float* emb    = (const float*)d_in[12];
    const float* W_fuse = (const float*)d_in[13];
    const float* b_fuse = (const float*)d_in[14];
    const float* W_p1   = (const float*)d_in[15];
    const float* b_p1   = (const float*)d_in[16];
    const float* W_p2   = (const float*)d_in[17];
    const float* b_p2   = (const float*)d_in[18];
    const float* W_p3   = (const float*)d_in[19];
    const float* b_p3   = (const float*)d_in[20];
    const float* W_d1   = (const float*)d_in[21];
    const float* b_d1   = (const float*)d_in[22];
    const float* W_d2   = (const float*)d_in[23];
    const float* b_d2   = (const float*)d_in[24];
    const float* W_d3   = (const float*)d_in[25];
    const float* b_d3   = (const float*)d_in[26];

    net_kernel<<<32, 512>>>(x, cidx, W_in, b_in, gat_W, gat_b, emb,
                            W_fuse, b_fuse, W_p1, b_p1, W_p2, b_p2,
                            W_p3, b_p3, W_d1, b_d1, W_d2, b_d2,
                            W_d3, b_d3, (float*)d_out);
}